// round 5
// baseline (speedup 1.0000x reference)
#include <cuda_runtime.h>
#include <cstdint>

// 524288 rows x 65 fp32 (h = row[0], x = row[1..64]); GRU cell + Linear(1,1).
//
// Round-5: persistent CTAs, 3-stage ring of cp.async.bulk tiles.
//   grid = 296 (148 SMs x 2 CTAs @ ~100 KB smem). Prologue prefetches 3
//   tiles; each iteration waits slot s, computes 128 rows (thread-per-row
//   from smem, stride-65 = conflict-free), then refills slot s with tile
//   i+3. 2-3 copies (66-100 KB) in flight per CTA at all times.

#define ROWS_TOTAL    524288
#define ROW_F         65
#define THREADS       128
#define ROWS_PER_TILE 128
#define NTILES        (ROWS_TOTAL / ROWS_PER_TILE)   // 4096
#define TILE_FLOATS   (ROWS_PER_TILE * ROW_F)        // 8320
#define TILE_BYTES    (TILE_FLOATS * 4)              // 33280
#define RING          3
#define GRID_CTAS     296                            // 148 * 2
#define DYN_SMEM_BYTES ((RING * TILE_FLOATS + 192) * 4)  // 100608

__device__ __forceinline__ uint32_t smem_u32(const void* p) {
    return (uint32_t)__cvta_generic_to_shared(p);
}

__device__ __forceinline__ void mbar_wait(uint32_t mbar_a, uint32_t parity) {
    asm volatile(
        "{\n\t"
        ".reg .pred p;\n\t"
        "W%=:\n\t"
        "mbarrier.try_wait.parity.acquire.cta.shared::cta.b64 p, [%0], %1;\n\t"
        "@!p bra W%=;\n\t"
        "}"
        :: "r"(mbar_a), "r"(parity) : "memory");
}

__device__ __forceinline__ void issue_bulk(uint32_t dst_smem, const float* src,
                                           uint32_t mbar_a) {
    asm volatile("mbarrier.arrive.expect_tx.shared.b64 _, [%0], %1;"
                 :: "r"(mbar_a), "r"((uint32_t)TILE_BYTES) : "memory");
    asm volatile(
        "cp.async.bulk.shared::cta.global.mbarrier::complete_tx::bytes "
        "[%0], [%1], %2, [%3];"
        :: "r"(dst_smem), "l"(src), "r"((uint32_t)TILE_BYTES), "r"(mbar_a)
        : "memory");
}

__global__ __launch_bounds__(THREADS) void gru_ring_kernel(
    const float* __restrict__ in,      // [ROWS_TOTAL, 65]
    const float* __restrict__ W_ih,    // [3, 64]
    const float* __restrict__ W_hh,    // [3]
    const float* __restrict__ b_ih,    // [3]
    const float* __restrict__ b_hh,    // [3]
    const float* __restrict__ w_out,   // [1]
    const float* __restrict__ b_out,   // [1]
    float* __restrict__ out)           // [ROWS_TOTAL]
{
    extern __shared__ __align__(16) float sdyn[];
    float* const sw = sdyn + RING * TILE_FLOATS;    // 192 floats W_ih
    __shared__ __align__(8) uint64_t mbar[RING];

    const int tid = threadIdx.x;

    if (tid < RING) {
        asm volatile("mbarrier.init.shared.b64 [%0], %1;"
                     :: "r"(smem_u32(&mbar[tid])), "r"(1) : "memory");
    }
    if (tid < 48) ((float4*)sw)[tid] = ((const float4*)W_ih)[tid];
    __syncthreads();   // mbarriers + weights visible

    // Prologue: prefetch first RING tiles into slots 0..RING-1.
    if (tid == 0) {
        #pragma unroll
        for (int k = 0; k < RING; ++k) {
            const int t = blockIdx.x + k * GRID_CTAS;
            if (t < NTILES) {
                issue_bulk(smem_u32(sdyn + k * TILE_FLOATS),
                           in + (size_t)t * TILE_FLOATS,
                           smem_u32(&mbar[k]));
            }
        }
    }

    // Uniform scalars (overlap the prologue copies).
    const float bi0 = b_ih[0],  bi1 = b_ih[1],  bi2 = b_ih[2];
    const float wh0 = W_hh[0],  wh1 = W_hh[1],  wh2 = W_hh[2];
    const float bh0 = b_hh[0],  bh1 = b_hh[1],  bh2 = b_hh[2];
    const float wo  = w_out[0], bo  = b_out[0];

    uint32_t ph[RING] = {0u, 0u, 0u};
    int i = 0;
    for (int tile = blockIdx.x; tile < NTILES; tile += GRID_CTAS, ++i) {
        const int s = (i >= RING) ? (i % RING) : i;   // i%3, cheap form
        float* const bcur = sdyn + s * TILE_FLOATS;
        const uint32_t mb = smem_u32(&mbar[s]);

        mbar_wait(mb, ph[s]);
        ph[s] ^= 1u;

        // ---- compute: thread t owns row t of this tile ----
        const float* __restrict__ xr = bcur + tid * ROW_F;
        const float h = xr[0];

        float s0 = 0.f, s1 = 0.f, s2 = 0.f;
        const float4* __restrict__ swq = (const float4*)sw;
        #pragma unroll
        for (int c = 0; c < 16; ++c) {
            const float4 w0 = swq[c];
            const float4 w1 = swq[16 + c];
            const float4 w2 = swq[32 + c];
            const float a0 = xr[1 + 4 * c + 0];
            const float a1 = xr[1 + 4 * c + 1];
            const float a2 = xr[1 + 4 * c + 2];
            const float a3 = xr[1 + 4 * c + 3];
            s0 = fmaf(a0, w0.x, fmaf(a1, w0.y, fmaf(a2, w0.z, fmaf(a3, w0.w, s0))));
            s1 = fmaf(a0, w1.x, fmaf(a1, w1.y, fmaf(a2, w1.z, fmaf(a3, w1.w, s1))));
            s2 = fmaf(a0, w2.x, fmaf(a1, w2.y, fmaf(a2, w2.z, fmaf(a3, w2.w, s2))));
        }

        const float gi0 = s0 + bi0;
        const float gi1 = s1 + bi1;
        const float gi2 = s2 + bi2;
        const float gh0 = fmaf(h, wh0, bh0);
        const float gh1 = fmaf(h, wh1, bh1);
        const float gh2 = fmaf(h, wh2, bh2);

        const float r = 1.0f / (1.0f + expf(-(gi0 + gh0)));
        const float z = 1.0f / (1.0f + expf(-(gi1 + gh1)));
        const float n = tanhf(fmaf(r, gh2, gi2));
        const float h_new = fmaf(z, h - n, n);   // (1-z)*n + z*h

        out[tile * ROWS_PER_TILE + tid] = fmaf(h_new, wo, bo);

        // All warps done reading slot s -> refill it with tile i+RING.
        __syncthreads();
        const int nxt = tile + RING * GRID_CTAS;
        if (tid == 0 && nxt < NTILES) {
            issue_bulk(smem_u32(bcur), in + (size_t)nxt * TILE_FLOATS, mb);
        }
    }
}

extern "C" void kernel_launch(void* const* d_in, const int* in_sizes, int n_in,
                              void* d_out, int out_size) {
    const float* inputs = (const float*)d_in[0];
    const float* W_ih   = (const float*)d_in[1];
    const float* W_hh   = (const float*)d_in[2];
    const float* b_ih   = (const float*)d_in[3];
    const float* b_hh   = (const float*)d_in[4];
    const float* w_out  = (const float*)d_in[5];
    const float* b_out  = (const float*)d_in[6];
    float* out = (float*)d_out;

    cudaFuncSetAttribute(gru_ring_kernel,
                         cudaFuncAttributeMaxDynamicSharedMemorySize,
                         DYN_SMEM_BYTES);
    gru_ring_kernel<<<GRID_CTAS, THREADS, DYN_SMEM_BYTES>>>(
        inputs, W_ih, W_hh, b_ih, b_hh, w_out, b_out, out);
}

// round 6
// speedup vs baseline: 1.0011x; 1.0011x over previous
#include <cuda_runtime.h>
#include <cstdint>

// 524288 rows x 65 fp32 (h = row[0], x = row[1..64]); GRU cell + Linear(1,1).
//
// Round-6: replace TMA bulk copies with per-thread cp.async (LDGSTS, 16 B),
// double-buffered, persistent CTAs. Hypothesis: the 5.2 TB/s plateau of
// rounds 3-5 is a TMA request-path ceiling; LDGSTS generates 2080
// independent 16B requests per tile through the LSU/L1tex path instead.
//   grid = 444 (148 SMs x 3 CTAs @ ~67 KB smem), 128 threads,
//   tiles of 128 rows (33,280 B = 2080 float4).

#define ROWS_TOTAL    524288
#define ROW_F         65
#define THREADS       128
#define ROWS_PER_TILE 128
#define NTILES        (ROWS_TOTAL / ROWS_PER_TILE)   // 4096
#define TILE_FLOATS   (ROWS_PER_TILE * ROW_F)        // 8320
#define TILE_Q        (TILE_FLOATS / 4)              // 2080 float4
#define GRID_CTAS     444
#define DYN_SMEM_BYTES ((2 * TILE_FLOATS + 192) * 4) // 67328

__device__ __forceinline__ uint32_t smem_u32(const void* p) {
    return (uint32_t)__cvta_generic_to_shared(p);
}

// Copy tile (2080 float4) global->smem via per-thread cp.async.
// 17 iterations; idx 2048..2079 only covered by tid<32.
__device__ __forceinline__ void prefetch_tile(float* dst, const float* src,
                                              int tid) {
    const float4* __restrict__ g = (const float4*)src;
    const uint32_t s0 = smem_u32(dst);
    #pragma unroll
    for (int j = 0; j < 17; ++j) {
        const int idx = j * THREADS + tid;
        if (idx < TILE_Q) {
            asm volatile("cp.async.cg.shared.global [%0], [%1], 16;"
                         :: "r"(s0 + (uint32_t)idx * 16u), "l"(g + idx)
                         : "memory");
        }
    }
    asm volatile("cp.async.commit_group;" ::: "memory");
}

__global__ __launch_bounds__(THREADS) void gru_ldgsts_kernel(
    const float* __restrict__ in,      // [ROWS_TOTAL, 65]
    const float* __restrict__ W_ih,    // [3, 64]
    const float* __restrict__ W_hh,    // [3]
    const float* __restrict__ b_ih,    // [3]
    const float* __restrict__ b_hh,    // [3]
    const float* __restrict__ w_out,   // [1]
    const float* __restrict__ b_out,   // [1]
    float* __restrict__ out)           // [ROWS_TOTAL]
{
    extern __shared__ __align__(16) float sdyn[];
    float* const buf[2] = { sdyn, sdyn + TILE_FLOATS };
    float* const sw = sdyn + 2 * TILE_FLOATS;       // 192 floats W_ih

    const int tid = threadIdx.x;

    if (tid < 48) ((float4*)sw)[tid] = ((const float4*)W_ih)[tid];

    // Prologue: prefetch first tile into buf0 (group 0).
    prefetch_tile(buf[0], in + (size_t)blockIdx.x * TILE_FLOATS, tid);

    // Uniform scalars (overlap prefetch).
    const float bi0 = b_ih[0],  bi1 = b_ih[1],  bi2 = b_ih[2];
    const float wh0 = W_hh[0],  wh1 = W_hh[1],  wh2 = W_hh[2];
    const float bh0 = b_hh[0],  bh1 = b_hh[1],  bh2 = b_hh[2];
    const float wo  = w_out[0], bo  = b_out[0];

    int i = 0;
    for (int tile = blockIdx.x; tile < NTILES; tile += GRID_CTAS, ++i) {
        const int cur = i & 1;

        // Issue next tile's loads into the other buffer (its previous
        // contents were fully consumed last iteration, barrier below).
        const int nxt = tile + GRID_CTAS;
        if (nxt < NTILES) {
            prefetch_tile(buf[1 - cur], in + (size_t)nxt * TILE_FLOATS, tid);
            asm volatile("cp.async.wait_group 1;" ::: "memory"); // cur done
        } else {
            asm volatile("cp.async.wait_group 0;" ::: "memory");
        }
        __syncthreads();   // all threads' copies of cur visible to all

        // ---- compute: thread t owns row t of this tile ----
        const float* __restrict__ xr = buf[cur] + tid * ROW_F;
        const float h = xr[0];

        float s0 = 0.f, s1 = 0.f, s2 = 0.f;
        const float4* __restrict__ swq = (const float4*)sw;
        #pragma unroll
        for (int c = 0; c < 16; ++c) {
            const float4 w0 = swq[c];
            const float4 w1 = swq[16 + c];
            const float4 w2 = swq[32 + c];
            const float a0 = xr[1 + 4 * c + 0];
            const float a1 = xr[1 + 4 * c + 1];
            const float a2 = xr[1 + 4 * c + 2];
            const float a3 = xr[1 + 4 * c + 3];
            s0 = fmaf(a0, w0.x, fmaf(a1, w0.y, fmaf(a2, w0.z, fmaf(a3, w0.w, s0))));
            s1 = fmaf(a0, w1.x, fmaf(a1, w1.y, fmaf(a2, w1.z, fmaf(a3, w1.w, s1))));
            s2 = fmaf(a0, w2.x, fmaf(a1, w2.y, fmaf(a2, w2.z, fmaf(a3, w2.w, s2))));
        }

        const float gi0 = s0 + bi0;
        const float gi1 = s1 + bi1;
        const float gi2 = s2 + bi2;
        const float gh0 = fmaf(h, wh0, bh0);
        const float gh1 = fmaf(h, wh1, bh1);
        const float gh2 = fmaf(h, wh2, bh2);

        const float r = 1.0f / (1.0f + expf(-(gi0 + gh0)));
        const float z = 1.0f / (1.0f + expf(-(gi1 + gh1)));
        const float n = tanhf(fmaf(r, gh2, gi2));
        const float h_new = fmaf(z, h - n, n);   // (1-z)*n + z*h

        out[tile * ROWS_PER_TILE + tid] = fmaf(h_new, wo, bo);

        // Buffer 'cur' fully consumed before next iteration overwrites it.
        __syncthreads();
    }
}

extern "C" void kernel_launch(void* const* d_in, const int* in_sizes, int n_in,
                              void* d_out, int out_size) {
    const float* inputs = (const float*)d_in[0];
    const float* W_ih   = (const float*)d_in[1];
    const float* W_hh   = (const float*)d_in[2];
    const float* b_ih   = (const float*)d_in[3];
    const float* b_hh   = (const float*)d_in[4];
    const float* w_out  = (const float*)d_in[5];
    const float* b_out  = (const float*)d_in[6];
    float* out = (float*)d_out;

    cudaFuncSetAttribute(gru_ldgsts_kernel,
                         cudaFuncAttributeMaxDynamicSharedMemorySize,
                         DYN_SMEM_BYTES);
    gru_ldgsts_kernel<<<GRID_CTAS, THREADS, DYN_SMEM_BYTES>>>(
        inputs, W_ih, W_hh, b_ih, b_hh, w_out, b_out, out);
}

// round 7
// speedup vs baseline: 1.0286x; 1.0275x over previous
#include <cuda_runtime.h>
#include <cstdint>

// 524288 rows x 65 fp32 (h = row[0], x = row[1..64]); GRU cell + Linear(1,1).
//
// Round-7: finer granularity to attack ramp/tail + request-stream smoothness.
//   64-row tiles (16,640 B), ring-3 cp.async groups (2 tiles in flight per
//   CTA during compute), grid = 592 (148 SMs x 4 CTAs @ ~50 KB smem).
//   8192 tiles -> 13.8 per CTA (tail fraction halved vs round 6).
//   threads 0..63 compute (thread-per-row); all 128 threads issue copies.

#define ROWS_TOTAL    524288
#define ROW_F         65
#define THREADS       128
#define ROWS_PER_TILE 64
#define NTILES        (ROWS_TOTAL / ROWS_PER_TILE)   // 8192
#define TILE_FLOATS   (ROWS_PER_TILE * ROW_F)        // 4160
#define TILE_Q        (TILE_FLOATS / 4)              // 1040 float4
#define RING          3
#define GRID_CTAS     592                            // 148 * 4
#define DYN_SMEM_BYTES ((RING * TILE_FLOATS + 192) * 4)  // 50688

__device__ __forceinline__ uint32_t smem_u32(const void* p) {
    return (uint32_t)__cvta_generic_to_shared(p);
}

// Copy one tile (1040 float4) global->smem via per-thread cp.async,
// then commit as one group.
__device__ __forceinline__ void prefetch_tile(float* dst, const float* src,
                                              int tid) {
    const float4* __restrict__ g = (const float4*)src;
    const uint32_t s0 = smem_u32(dst);
    #pragma unroll
    for (int j = 0; j < 9; ++j) {
        const int idx = j * THREADS + tid;
        if (idx < TILE_Q) {
            asm volatile("cp.async.cg.shared.global [%0], [%1], 16;"
                         :: "r"(s0 + (uint32_t)idx * 16u), "l"(g + idx)
                         : "memory");
        }
    }
    asm volatile("cp.async.commit_group;" ::: "memory");
}

__global__ __launch_bounds__(THREADS) void gru_fine_kernel(
    const float* __restrict__ in,      // [ROWS_TOTAL, 65]
    const float* __restrict__ W_ih,    // [3, 64]
    const float* __restrict__ W_hh,    // [3]
    const float* __restrict__ b_ih,    // [3]
    const float* __restrict__ b_hh,    // [3]
    const float* __restrict__ w_out,   // [1]
    const float* __restrict__ b_out,   // [1]
    float* __restrict__ out)           // [ROWS_TOTAL]
{
    extern __shared__ __align__(16) float sdyn[];
    float* const sw = sdyn + RING * TILE_FLOATS;    // 192 floats W_ih

    const int tid = threadIdx.x;

    if (tid < 48) ((float4*)sw)[tid] = ((const float4*)W_ih)[tid];

    // Prologue: prefetch tiles 0 and 1 into slots 0 and 1 (two groups).
    {
        const int t0 = blockIdx.x;
        const int t1 = blockIdx.x + GRID_CTAS;
        prefetch_tile(sdyn, in + (size_t)t0 * TILE_FLOATS, tid);
        if (t1 < NTILES)
            prefetch_tile(sdyn + TILE_FLOATS, in + (size_t)t1 * TILE_FLOATS, tid);
    }

    // Uniform scalars (overlap prologue copies).
    const float bi0 = b_ih[0],  bi1 = b_ih[1],  bi2 = b_ih[2];
    const float wh0 = W_hh[0],  wh1 = W_hh[1],  wh2 = W_hh[2];
    const float bh0 = b_hh[0],  bh1 = b_hh[1],  bh2 = b_hh[2];
    const float wo  = w_out[0], bo  = b_out[0];

    int i = 0;
    for (int tile = blockIdx.x; tile < NTILES; tile += GRID_CTAS, ++i) {
        const int s = i % RING;
        float* const bcur = sdyn + s * TILE_FLOATS;

        // Issue tile i+2 into slot (i+2)%RING, then wait until the oldest
        // outstanding groups beyond 2 retire => slot s's group is complete.
        const int n2 = tile + 2 * GRID_CTAS;
        if (n2 < NTILES) {
            prefetch_tile(sdyn + ((i + 2) % RING) * TILE_FLOATS,
                          in + (size_t)n2 * TILE_FLOATS, tid);
            asm volatile("cp.async.wait_group 2;" ::: "memory");
        } else {
            asm volatile("cp.async.wait_group 0;" ::: "memory");
        }
        __syncthreads();   // slot s visible to all threads

        if (tid < ROWS_PER_TILE) {
            // ---- compute: thread t owns row t of this tile ----
            const float* __restrict__ xr = bcur + tid * ROW_F;
            const float h = xr[0];

            float s0 = 0.f, s1 = 0.f, s2 = 0.f;
            const float4* __restrict__ swq = (const float4*)sw;
            #pragma unroll
            for (int c = 0; c < 16; ++c) {
                const float4 w0 = swq[c];
                const float4 w1 = swq[16 + c];
                const float4 w2 = swq[32 + c];
                const float a0 = xr[1 + 4 * c + 0];
                const float a1 = xr[1 + 4 * c + 1];
                const float a2 = xr[1 + 4 * c + 2];
                const float a3 = xr[1 + 4 * c + 3];
                s0 = fmaf(a0, w0.x, fmaf(a1, w0.y, fmaf(a2, w0.z, fmaf(a3, w0.w, s0))));
                s1 = fmaf(a0, w1.x, fmaf(a1, w1.y, fmaf(a2, w1.z, fmaf(a3, w1.w, s1))));
                s2 = fmaf(a0, w2.x, fmaf(a1, w2.y, fmaf(a2, w2.z, fmaf(a3, w2.w, s2))));
            }

            const float gi0 = s0 + bi0;
            const float gi1 = s1 + bi1;
            const float gi2 = s2 + bi2;
            const float gh0 = fmaf(h, wh0, bh0);
            const float gh1 = fmaf(h, wh1, bh1);
            const float gh2 = fmaf(h, wh2, bh2);

            const float r = 1.0f / (1.0f + expf(-(gi0 + gh0)));
            const float z = 1.0f / (1.0f + expf(-(gi1 + gh1)));
            const float n = tanhf(fmaf(r, gh2, gi2));
            const float h_new = fmaf(z, h - n, n);   // (1-z)*n + z*h

            out[tile * ROWS_PER_TILE + tid] = fmaf(h_new, wo, bo);
        }

        // Slot s fully consumed before iteration i+1 issues tile i+3 into it.
        __syncthreads();
    }
}

extern "C" void kernel_launch(void* const* d_in, const int* in_sizes, int n_in,
                              void* d_out, int out_size) {
    const float* inputs = (const float*)d_in[0];
    const float* W_ih   = (const float*)d_in[1];
    const float* W_hh   = (const float*)d_in[2];
    const float* b_ih   = (const float*)d_in[3];
    const float* b_hh   = (const float*)d_in[4];
    const float* w_out  = (const float*)d_in[5];
    const float* b_out  = (const float*)d_in[6];
    float* out = (float*)d_out;

    cudaFuncSetAttribute(gru_fine_kernel,
                         cudaFuncAttributeMaxDynamicSharedMemorySize,
                         DYN_SMEM_BYTES);
    gru_fine_kernel<<<GRID_CTAS, THREADS, DYN_SMEM_BYTES>>>(
        inputs, W_ih, W_hh, b_ih, b_hh, w_out, b_out, out);
}